// round 3
// baseline (speedup 1.0000x reference)
#include <cuda_runtime.h>

#define HH 128
#define WW 128
#define CC 16
#define FF 16
#define NB 2
#define SNX 32
#define SNY 32

__global__ __launch_bounds__(256) void patch_filter_kernel(
    const float* __restrict__ pet, const float* __restrict__ bfeat,
    float* __restrict__ out)
{
    __shared__ float pet_s[64 * 16];     // 4 KB
    __shared__ float part_d[4 * 256];    // 4 KB  cross-g diag partials
    __shared__ float part_k[4 * 256];    // 4 KB  cross-g kp partials
    __shared__ float ratio_s[256];       // 1 KB

    const int sny = blockIdx.x;
    const int snx = blockIdx.y;
    const int bz  = blockIdx.z;
    const int t   = threadIdx.x;
    const int q   = t & 63;              // float4 slot within pixel (0..63)
    const int g   = t >> 6;              // pixel-group: owns pix == g (mod 4)
    const int c   = q >> 2;              // channel this q-slot belongs to

    const int r0 = snx * 4 - 2;          // SAME pad = 2
    const int c0 = sny * 4 - 2;

    // ---- Stage pet patch (8x8 x 16 floats) ----
    {
        int pix = t >> 2, qq = t & 3;
        int r = r0 + (pix >> 3), col = c0 + (pix & 7);
        float4 v = make_float4(0.f, 0.f, 0.f, 0.f);
        if ((unsigned)r < HH && (unsigned)col < WW)
            v = *(const float4*)(pet + ((bz * HH + r) * WW + col) * CC + qq * 4);
        *(float4*)(pet_s + pix * 16 + qq * 4) = v;
    }
    __syncthreads();

    // ---- Load b into registers, fuse pass-1 partial reductions ----
    float4 b4[16];
    float4 dsum = make_float4(0.f, 0.f, 0.f, 0.f);
    float4 ksum = make_float4(0.f, 0.f, 0.f, 0.f);
    const float* bbase = bfeat + (size_t)bz * HH * WW * CC * FF + q * 4;
#pragma unroll
    for (int k = 0; k < 16; k++) {
        int pix = 4 * k + g;
        int r = r0 + (pix >> 3), col = c0 + (pix & 7);
        float4 bv = make_float4(0.f, 0.f, 0.f, 0.f);
        if ((unsigned)r < HH && (unsigned)col < WW)
            bv = *(const float4*)(bbase + (r * WW + col) * (CC * FF));
        b4[k] = bv;
        float pv = pet_s[pix * 16 + c];   // broadcast-friendly
        dsum.x += bv.x; dsum.y += bv.y; dsum.z += bv.z; dsum.w += bv.w;
        ksum.x = fmaf(pv, bv.x, ksum.x);
        ksum.y = fmaf(pv, bv.y, ksum.y);
        ksum.z = fmaf(pv, bv.z, ksum.z);
        ksum.w = fmaf(pv, bv.w, ksum.w);
    }
    *(float4*)(part_d + g * 256 + q * 4) = dsum;
    *(float4*)(part_k + g * 256 + q * 4) = ksum;
    __syncthreads();

    // ---- ratio[cf] = divide_no_nan(kp, diag), thread t handles cf = t ----
    {
        float d  = part_d[t] + part_d[256 + t] + part_d[512 + t] + part_d[768 + t];
        float kk = part_k[t] + part_k[256 + t] + part_k[512 + t] + part_k[768 + t];
        ratio_s[t] = (d != 0.f) ? (kk / d) : 0.f;
    }
    __syncthreads();

    const float4 rat = *(const float4*)(ratio_s + q * 4);

    // ---- Pass 2 + direct accumulation into out (each out elem gets 4 adds) ----
    float* dst = out + (size_t)bz * HH * WW * CC;
    const bool lead = ((q & 3) == 0);
#pragma unroll
    for (int k = 0; k < 16; k++) {
        float4 bv = b4[k];
        float Kp = bv.x * rat.x + bv.y * rat.y + bv.z * rat.z + bv.w * rat.w;
        Kp += __shfl_xor_sync(0xffffffffu, Kp, 1);
        Kp += __shfl_xor_sync(0xffffffffu, Kp, 2);
        if (lead) {
            int pix = 4 * k + g;
            int r   = (r0 + (pix >> 3)) & (HH - 1);   // wrap == jnp.roll
            int col = (c0 + (pix & 7)) & (WW - 1);
            atomicAdd(dst + (r * WW + col) * CC + c, 0.25f * Kp);  // -> RED.ADD
        }
    }
}

extern "C" void kernel_launch(void* const* d_in, const int* in_sizes, int n_in,
                              void* d_out, int out_size)
{
    // Input order per reference signature: mr (unused), pet, b, px, py, sx, sy
    const float* pet   = (const float*)d_in[1];
    const float* bfeat = (const float*)d_in[2];

    // out gets exactly 4 accumulations per element; zero-init first.
    cudaMemsetAsync(d_out, 0, (size_t)out_size * sizeof(float));

    dim3 grid(SNY, SNX, NB);
    patch_filter_kernel<<<grid, 256>>>(pet, bfeat, (float*)d_out);
}